// round 12
// baseline (speedup 1.0000x reference)
#include <cuda_runtime.h>
#include <float.h>
#include <stdint.h>

// Problem constants
#define PN 32768   // points per side
#define PM 8192    // shortcut (query) points per side
#define PC 256     // feature channels

#define TS 2048          // tile points in smem
#define NT (PN / TS)     // 16 tiles
#define WARPS 8
#define BLOCK (WARPS * 32)
#define QPB 16           // queries per block (4 per warp, x2 split-N warp sets)

// Tile-order pair-interleaved coords (for smem fill): A=(x0,x1,y0,y1), B=(z0,z1,b20,b21)
__device__ float4 g_A[2][PN / 2];
__device__ float4 g_B[2][PN / 2];
// Chunk-major reordered copy (for coalesced epilogue rescans):
// halfchunk c = (h<<4)|(s<<1)|th ; layout [c][tile_in_half rr][v] of float4 pairs.
__device__ float4 g_RA[2][PN / 2];
__device__ float4 g_RB[2][PN / 2];

__forceinline__ __device__ float sqnorm3(float x, float y, float z) {
    return (x * x + y * y) + z * z;
}

// Scalar distance — bit-identical to the packed f32x2 path (IEEE per-component),
// same sequence as the R1 kernel that measured rel_err == 0.0.
__forceinline__ __device__ float dist_d(float x, float y, float z, float b2,
                                        float qx, float qy, float qz, float a2) {
    const float dot = fmaf(x, qx, fmaf(y, qy, z * qz));
    const float t   = a2 + b2;
    return fmaf(-2.0f, dot, t);
}

// Packed f32x2 ops (sm_103a)
#define FMA2(r, a, b, c) asm("fma.rn.f32x2 %0, %1, %2, %3;" : "=l"(r) : "l"(a), "l"(b), "l"(c))
#define MUL2(r, a, b)    asm("mul.rn.f32x2 %0, %1, %2;"     : "=l"(r) : "l"(a), "l"(b))
#define ADD2(r, a, b)    asm("add.rn.f32x2 %0, %1, %2;"     : "=l"(r) : "l"(a), "l"(b))
#define PACK2(r, lo, hi) asm("mov.b64 %0, {%1, %2};" : "=l"(r) : "f"(lo), "f"(hi))
#define UNPACK2(lo, hi, r) asm("mov.b64 {%0, %1}, %2;" : "=f"(lo), "=f"(hi) : "l"(r))

__forceinline__ __device__ bool lex_lt(float da, int ia, float db, int ib) {
    return (da < db) || (da == db && ia < ib);
}

__global__ void pack_kernel(const float* __restrict__ src_coords,
                            const float* __restrict__ tgt_coords) {
    const int p = blockIdx.x * blockDim.x + threadIdx.x;   // point-pair index
    const int side = blockIdx.y;
    const float* __restrict__ c = side ? tgt_coords : src_coords;
    const int n0 = 2 * p;
    const float x0 = c[n0 * 3 + 0], y0 = c[n0 * 3 + 1], z0 = c[n0 * 3 + 2];
    const float x1 = c[n0 * 3 + 3], y1 = c[n0 * 3 + 4], z1 = c[n0 * 3 + 5];
    const float4 A = make_float4(x0, x1, y0, y1);
    const float4 B = make_float4(z0, z1, sqnorm3(x0, y0, z0), sqnorm3(x1, y1, z1));
    g_A[side][p] = A;
    g_B[side][p] = B;
    // chunk-major copy: identical bits (incl. b2) by construction
    const int r  = n0 >> 11;          // tile
    const int j  = n0 & 2047;
    const int h  = j >> 10;           // half within tile
    const int v  = (j >> 4) & 63;     // v-step within half
    const int s  = (j >> 1) & 7;      // slot
    const int th = r >> 3;            // tile-half
    const int ck = (h << 4) | (s << 1) | th;
    const int ridx = (ck * 8 + (r & 7)) * 64 + v;
    g_RA[side][ridx] = A;
    g_RB[side][ridx] = B;
}

__global__ __launch_bounds__(BLOCK, 5) void closest_pool_main(
    const float* __restrict__ src_feats,
    const float* __restrict__ tgt_feats,
    const float* __restrict__ src_sc,
    const float* __restrict__ tgt_sc,
    float* __restrict__ out)
{
    __shared__ __align__(16) float4 shA[TS / 2];
    __shared__ __align__(16) float4 shB[TS / 2];
    __shared__ float minv[QPB][32];   // [query][halfchunk] lane-min values

    const int side = blockIdx.y;
    const float* __restrict__ feats = side ? tgt_feats : src_feats;
    const float* __restrict__ qc    = side ? tgt_sc    : src_sc;
    float* __restrict__ out_side = out + (size_t)side * PM * PC;

    const float4* __restrict__ gA  = g_A[side];
    const float4* __restrict__ gB  = g_B[side];
    const float4* __restrict__ gRA = g_RA[side];
    const float4* __restrict__ gRB = g_RB[side];

    const int warp = threadIdx.x >> 5;
    const int lane = threadIdx.x & 31;
    const int half = warp >> 2;          // split-N: which half of each tile this warp scans
    const int grp  = lane >> 3;          // lane's query group (0..3)
    const int s    = lane & 7;           // lane's slot (8 slots x 16B = one 128B line)
    const int qloc = (warp & 3) * 4 + grp;           // block-local query (0..15)
    const int qi   = blockIdx.x * QPB + qloc;

    // Per-lane single query (packed broadcast regs)
    unsigned long long qx2, qy2, qz2, qa22, NEG2;
    {
        const float qx = qc[qi * 3 + 0];
        const float qy = qc[qi * 3 + 1];
        const float qz = qc[qi * 3 + 2];
        const float a2 = sqnorm3(qx, qy, qz);
        PACK2(qx2, qx, qx);
        PACK2(qy2, qy, qy);
        PACK2(qz2, qz, qz);
        PACK2(qa22, a2, a2);
        const float m2 = -2.0f;
        PACK2(NEG2, m2, m2);
    }

    // Value-only minima, split by tile-half (th) for finer rescan chunks
    float dl[2] = {FLT_MAX, FLT_MAX};
    float dh[2] = {FLT_MAX, FLT_MAX};

    const int hbase = half * (TS / 4);   // float4 index of this warp's half within the tile

    #pragma unroll 1
    for (int th = 0; th < 2; th++) {
        #pragma unroll 1
        for (int rr = 0; rr < NT / 2; rr++) {
            const int r = th * (NT / 2) + rr;
            __syncthreads();
            // Fill whole tile (both halves), straight copy — broadcast reads need no swizzle
            {
                const int g0 = r * (TS / 2);
                #pragma unroll
                for (int t = threadIdx.x; t < TS / 2; t += BLOCK) {
                    shA[t] = gA[g0 + t];
                    shB[t] = gB[g0 + t];
                }
            }
            __syncthreads();

            // 64 v-steps over this warp's half; lane reads slot s of each 8-slot line.
            // All 4 groups read the SAME address -> smem broadcast (1 phase per LDS.128).
            #pragma unroll 1
            for (int v8 = 0; v8 < 64; v8 += 8) {
                #pragma unroll
                for (int vv = 0; vv < 8; vv++) {
                    const int idx = hbase + (v8 + vv) * 8 + s;
                    const float4 va = shA[idx];    // (x0,x1,y0,y1)
                    const float4 vb = shB[idx];    // (z0,z1,b20,b21)
                    unsigned long long xp, yp, zp, b2p;
                    PACK2(xp,  va.x, va.y);
                    PACK2(yp,  va.z, va.w);
                    PACK2(zp,  vb.x, vb.y);
                    PACK2(b2p, vb.z, vb.w);
                    unsigned long long acc, dot2, d2v;
                    MUL2(acc, zp, qz2);
                    FMA2(dot2, yp, qy2, acc);
                    FMA2(dot2, xp, qx2, dot2);
                    ADD2(acc, qa22, b2p);
                    FMA2(d2v, NEG2, dot2, acc);
                    float dlo, dhi;
                    UNPACK2(dlo, dhi, d2v);
                    dl[th] = fminf(dl[th], dlo);
                    dh[th] = fminf(dh[th], dhi);
                }
            }
        }
    }

    // Publish per-(query, halfchunk) minima. halfchunk c = (h<<4)|(s<<1)|th.
    __syncthreads();
    minv[qloc][(half << 4) | (s << 1) | 0] = fminf(dl[0], dh[0]);
    minv[qloc][(half << 4) | (s << 1) | 1] = fminf(dl[1], dh[1]);
    __syncthreads();

    // ---- Epilogue: each warp finishes 2 queries (block-local 2w, 2w+1) ----
    #pragma unroll 1
    for (int e = 0; e < 2; e++) {
        const int q  = warp * 2 + e;
        const int qo = blockIdx.x * QPB + q;
        const float qx = qc[qo * 3 + 0];
        const float qy = qc[qo * 3 + 1];
        const float qz = qc[qo * 3 + 2];
        const float a2 = sqnorm3(qx, qy, qz);

        const float m = minv[q][lane];   // lane <-> halfchunk, all 32 valid

        // Warp top-2 VALUES with multiplicity: bd <= sd
        float bd = m, sd = FLT_MAX;
        #pragma unroll
        for (int off = 16; off > 0; off >>= 1) {
            const float ob = __shfl_xor_sync(0xFFFFFFFFu, bd, off);
            const float os = __shfl_xor_sync(0xFFFFFFFFu, sd, off);
            const float nb = fminf(bd, ob);
            const float mx = fmaxf(bd, ob);
            sd = fminf(mx, fminf(sd, os));
            bd = nb;
        }
        // Halfchunks that can hold a global top-2 point have min in {bd, sd}
        unsigned mask = __ballot_sync(0xFFFFFFFFu, m == bd || m == sd);

        float g1d = FLT_MAX, g2d = FLT_MAX;
        int   g1i = 0x7fffffff, g2i = 0x7fffffff;

        while (mask) {
            const int ck = __ffs(mask) - 1;
            mask &= mask - 1;
            const int ch = ck >> 4;
            const int cs = (ck >> 1) & 7;
            const int th = ck & 1;

            // Coalesced rescan of halfchunk ck: 8 tiles x 64 v x 2 pts, contiguous in g_R*.
            float p1d = FLT_MAX, p2d = FLT_MAX;
            int   p1i = 0x7fffffff, p2i = 0x7fffffff;
            #pragma unroll 1
            for (int rr = 0; rr < NT / 2; rr++) {
                const int rbase = (ck * 8 + rr) * 64;
                const int r = th * (NT / 2) + rr;
                #pragma unroll
                for (int round = 0; round < 2; round++) {
                    const int v = round * 32 + lane;        // ascending per lane
                    const float4 va = gRA[rbase + v];
                    const float4 vb = gRB[rbase + v];
                    const int n0 = r * TS + ch * 1024 + v * 16 + cs * 2;
                    {
                        const float d = dist_d(va.x, va.z, vb.x, vb.z, qx, qy, qz, a2);
                        const bool lt1 = d < p1d;
                        const bool lt2 = d < p2d;
                        p2d = lt1 ? p1d : (lt2 ? d : p2d);
                        p2i = lt1 ? p1i : (lt2 ? n0 : p2i);
                        p1d = lt1 ? d   : p1d;
                        p1i = lt1 ? n0  : p1i;
                    }
                    {
                        const int n1 = n0 + 1;
                        const float d = dist_d(va.y, va.w, vb.y, vb.w, qx, qy, qz, a2);
                        const bool lt1 = d < p1d;
                        const bool lt2 = d < p2d;
                        p2d = lt1 ? p1d : (lt2 ? d : p2d);
                        p2i = lt1 ? p1i : (lt2 ? n1 : p2i);
                        p1d = lt1 ? d   : p1d;
                        p1i = lt1 ? n1  : p1i;
                    }
                }
            }
            // Lex merge of per-lane top-2 lists
            #pragma unroll
            for (int off = 16; off > 0; off >>= 1) {
                const float o1d = __shfl_xor_sync(0xFFFFFFFFu, p1d, off);
                const float o2d = __shfl_xor_sync(0xFFFFFFFFu, p2d, off);
                const int   o1i = __shfl_xor_sync(0xFFFFFFFFu, p1i, off);
                const int   o2i = __shfl_xor_sync(0xFFFFFFFFu, p2i, off);
                const bool aF = lex_lt(p1d, p1i, o1d, o1i);
                const float c1 = aF ? o1d : p1d;  const int c1i = aF ? o1i : p1i;
                const float c2 = aF ? p2d : o2d;  const int c2i = aF ? p2i : o2i;
                const float n1 = aF ? p1d : o1d;  const int n1i = aF ? p1i : o1i;
                const bool t1 = lex_lt(c1, c1i, c2, c2i);
                p1d = n1; p1i = n1i;
                p2d = t1 ? c1 : c2; p2i = t1 ? c1i : c2i;
            }
            const float w1d = __shfl_sync(0xFFFFFFFFu, p1d, 0);
            const int   w1i = __shfl_sync(0xFFFFFFFFu, p1i, 0);
            const float w2d = __shfl_sync(0xFFFFFFFFu, p2d, 0);
            const int   w2i = __shfl_sync(0xFFFFFFFFu, p2i, 0);

            // Merge disjoint-set top-2 lists
            const bool aF = lex_lt(g1d, g1i, w1d, w1i);
            const float c1 = aF ? w1d : g1d;  const int c1i = aF ? w1i : g1i;
            const float c2 = aF ? g2d : w2d;  const int c2i = aF ? g2i : w2i;
            const float n1 = aF ? g1d : w1d;  const int n1i = aF ? g1i : w1i;
            const bool t1 = lex_lt(c1, c1i, c2, c2i);
            g1d = n1; g1i = n1i;
            g2d = t1 ? c1 : c2; g2i = t1 ? c1i : c2i;
        }

        const int sel = g2i;   // stable 2nd-nearest index

        // Gather feature row (256 floats), warp-coalesced
        const float4* __restrict__ srow = reinterpret_cast<const float4*>(feats + (size_t)sel * PC);
        float4* __restrict__ drow = reinterpret_cast<float4*>(out_side + (size_t)qo * PC);
        #pragma unroll
        for (int k = lane; k < PC / 4; k += 32) {
            drow[k] = srow[k];
        }
    }
}

extern "C" void kernel_launch(void* const* d_in, const int* in_sizes, int n_in,
                              void* d_out, int out_size)
{
    const float* src        = (const float*)d_in[0];
    const float* tgt        = (const float*)d_in[1];
    const float* src_coords = (const float*)d_in[2];
    const float* tgt_coords = (const float*)d_in[3];
    const float* src_sc     = (const float*)d_in[4];
    const float* tgt_sc     = (const float*)d_in[5];
    float* out = (float*)d_out;

    dim3 pgrid(PN / 2 / 256, 2);
    pack_kernel<<<pgrid, 256>>>(src_coords, tgt_coords);

    dim3 grid(PM / QPB, 2);
    closest_pool_main<<<grid, BLOCK>>>(src, tgt, src_sc, tgt_sc, out);
}

// round 13
// speedup vs baseline: 1.9435x; 1.9435x over previous
#include <cuda_runtime.h>
#include <float.h>
#include <stdint.h>

// Problem constants
#define PN 32768   // points per side
#define PM 8192    // shortcut (query) points per side
#define PC 256     // feature channels

#define TS 1024          // tile points per TEAM per iteration
#define TILES 16         // tiles per team (TILES * TS = PN/2 points per team)
#define WARPS 8
#define BLOCK (WARPS * 32)
#define QPW 4            // queries per warp
#define QPB 16           // queries per block (each query scanned by 2 warps, one per team)

// Pair-interleaved packed coords: A=(x0,x1,y0,y1), B=(z0,z1,b20,b21).
// b2 computed once; main loop and rescan read identical bits.
__device__ float4 g_A[2][PN / 2];
__device__ float4 g_B[2][PN / 2];

__forceinline__ __device__ float sqnorm3(float x, float y, float z) {
    return (x * x + y * y) + z * z;
}

// Scalar distance — bit-identical to the packed f32x2 path (IEEE per-component),
// same sequence as the R1 kernel that measured rel_err == 0.0.
__forceinline__ __device__ float dist_d(float x, float y, float z, float b2,
                                        float qx, float qy, float qz, float a2) {
    const float dot = fmaf(x, qx, fmaf(y, qy, z * qz));
    const float t   = a2 + b2;
    return fmaf(-2.0f, dot, t);
}

// Packed f32x2 ops (sm_103a)
#define FMA2(r, a, b, c) asm("fma.rn.f32x2 %0, %1, %2, %3;" : "=l"(r) : "l"(a), "l"(b), "l"(c))
#define MUL2(r, a, b)    asm("mul.rn.f32x2 %0, %1, %2;"     : "=l"(r) : "l"(a), "l"(b))
#define ADD2(r, a, b)    asm("add.rn.f32x2 %0, %1, %2;"     : "=l"(r) : "l"(a), "l"(b))
#define PACK2(r, lo, hi) asm("mov.b64 %0, {%1, %2};" : "=l"(r) : "f"(lo), "f"(hi))
#define UNPACK2(lo, hi, r) asm("mov.b64 {%0, %1}, %2;" : "=f"(lo), "=f"(hi) : "l"(r))

__forceinline__ __device__ bool lex_lt(float da, int ia, float db, int ib) {
    return (da < db) || (da == db && ia < ib);
}

__global__ void pack_kernel(const float* __restrict__ src_coords,
                            const float* __restrict__ tgt_coords) {
    const int p = blockIdx.x * blockDim.x + threadIdx.x;   // point-pair index
    const int side = blockIdx.y;
    const float* __restrict__ c = side ? tgt_coords : src_coords;
    const int n0 = 2 * p;
    const float x0 = c[n0 * 3 + 0], y0 = c[n0 * 3 + 1], z0 = c[n0 * 3 + 2];
    const float x1 = c[n0 * 3 + 3], y1 = c[n0 * 3 + 4], z1 = c[n0 * 3 + 5];
    g_A[side][p] = make_float4(x0, x1, y0, y1);
    g_B[side][p] = make_float4(z0, z1, sqnorm3(x0, y0, z0), sqnorm3(x1, y1, z1));
}

__global__ __launch_bounds__(BLOCK, 4) void closest_pool_main(
    const float* __restrict__ src_feats,
    const float* __restrict__ tgt_feats,
    const float* __restrict__ src_sc,
    const float* __restrict__ tgt_sc,
    float* __restrict__ out)
{
    // One tile buffer per team. Rotation swizzle within each lane's 16-slot chunk:
    // logical (L, v) -> physical L*16 + ((v + L) & 15)  => 4-phase (optimal) LDS.128.
    __shared__ __align__(16) float4 shA[2][TS / 2];
    __shared__ __align__(16) float4 shB[2][TS / 2];
    __shared__ float minv[QPB][64];    // [query][chunk = team*32 + lane]

    const int side = blockIdx.y;
    const float* __restrict__ feats = side ? tgt_feats : src_feats;
    const float* __restrict__ qc    = side ? tgt_sc    : src_sc;
    float* __restrict__ out_side = out + (size_t)side * PM * PC;

    const float4* __restrict__ gA = g_A[side];
    const float4* __restrict__ gB = g_B[side];

    const int warp = threadIdx.x >> 5;
    const int lane = threadIdx.x & 31;
    const int team = warp >> 2;                 // 0: points [0,16K), 1: [16K,32K)
    const int qloc0 = (warp & 3) * QPW;         // block-local query base for this warp

    // Packed query broadcasts for 4 queries
    unsigned long long qx2[QPW], qy2[QPW], qz2[QPW], qa22[QPW], NEG2;
    #pragma unroll
    for (int q = 0; q < QPW; q++) {
        const int qi = blockIdx.x * QPB + qloc0 + q;
        const float qx = qc[qi * 3 + 0];
        const float qy = qc[qi * 3 + 1];
        const float qz = qc[qi * 3 + 2];
        const float a2 = sqnorm3(qx, qy, qz);
        PACK2(qx2[q], qx, qx);
        PACK2(qy2[q], qy, qy);
        PACK2(qz2[q], qz, qz);
        PACK2(qa22[q], a2, a2);
    }
    { const float m2 = -2.0f; PACK2(NEG2, m2, m2); }

    float dl[QPW], dh[QPW];
    #pragma unroll
    for (int q = 0; q < QPW; q++) { dl[q] = FLT_MAX; dh[q] = FLT_MAX; }

    #pragma unroll 1
    for (int r = 0; r < TILES; r++) {
        __syncthreads();
        // Fill both team buffers: buffer b holds tile r of team b (pairs b*8192 + r*512 + p)
        #pragma unroll
        for (int t = threadIdx.x; t < TS; t += BLOCK) {     // TS == 2 * (TS/2) slots
            const int b = t >> 9;
            const int p = t & 511;
            const int L = p >> 4, v = p & 15;
            const int phys = (L << 4) | ((v + L) & 15);
            shA[b][phys] = gA[b * (PN / 4) + r * 512 + p];
            shB[b][phys] = gB[b * (PN / 4) + r * 512 + p];
        }
        __syncthreads();

        // 16 v-steps; lane owns pairs [lane*16, lane*16+16) of its team's tile.
        #pragma unroll 8
        for (int v = 0; v < 16; v++) {
            const int idx = (lane << 4) | ((v + lane) & 15);
            const float4 va = shA[team][idx];   // (x0,x1,y0,y1)
            const float4 vb = shB[team][idx];   // (z0,z1,b20,b21)
            unsigned long long xp, yp, zp, b2p;
            PACK2(xp,  va.x, va.y);
            PACK2(yp,  va.z, va.w);
            PACK2(zp,  vb.x, vb.y);
            PACK2(b2p, vb.z, vb.w);
            #pragma unroll
            for (int q = 0; q < QPW; q++) {
                unsigned long long acc, dot2, d2v;
                MUL2(acc, zp, qz2[q]);
                FMA2(dot2, yp, qy2[q], acc);
                FMA2(dot2, xp, qx2[q], dot2);
                ADD2(acc, qa22[q], b2p);
                FMA2(d2v, NEG2, dot2, acc);
                float dlo, dhi;
                UNPACK2(dlo, dhi, d2v);
                dl[q] = fminf(dl[q], dlo);
                dh[q] = fminf(dh[q], dhi);
            }
        }
    }

    // Publish chunk minima: chunk c = team*32 + lane owns 512 pts
    // { team*16384 + r*1024 + lane*32 + [0,32) : r in [0,16) }
    __syncthreads();
    #pragma unroll
    for (int q = 0; q < QPW; q++)
        minv[qloc0 + q][team * 32 + lane] = fminf(dl[q], dh[q]);
    __syncthreads();

    // ---- Epilogue: each warp finishes 2 queries ----
    #pragma unroll 1
    for (int e = 0; e < 2; e++) {
        const int q  = warp * 2 + e;
        const int qo = blockIdx.x * QPB + q;
        const float qx = qc[qo * 3 + 0];
        const float qy = qc[qo * 3 + 1];
        const float qz = qc[qo * 3 + 2];
        const float a2 = sqnorm3(qx, qy, qz);

        const float m0 = minv[q][lane];        // chunk lane      (team 0)
        const float m1 = minv[q][32 + lane];   // chunk 32+lane   (team 1)

        // Top-2 (with multiplicity) over all 64 chunk minima
        float bd = fminf(m0, m1);
        float sd = fmaxf(m0, m1);
        #pragma unroll
        for (int off = 16; off > 0; off >>= 1) {
            const float ob = __shfl_xor_sync(0xFFFFFFFFu, bd, off);
            const float os = __shfl_xor_sync(0xFFFFFFFFu, sd, off);
            const bool aF = bd <= ob;
            const float c1 = aF ? ob : bd;     // max of firsts
            const float c2 = aF ? sd : os;     // winner's second
            bd = aF ? bd : ob;
            sd = fminf(c1, c2);
        }
        // Chunks that can hold a global top-2 point have min in {bd, sd}
        unsigned mask0 = __ballot_sync(0xFFFFFFFFu, m0 == bd || m0 == sd);
        unsigned mask1 = __ballot_sync(0xFFFFFFFFu, m1 == bd || m1 == sd);

        float g1d = FLT_MAX, g2d = FLT_MAX;
        int   g1i = 0x7fffffff, g2i = 0x7fffffff;

        #pragma unroll 1
        for (int half = 0; half < 2; half++) {
            unsigned mask = half ? mask1 : mask0;
            while (mask) {
                const int L = __ffs(mask) - 1;
                mask &= mask - 1;
                const int T = half;

                // Coalesced rescan of chunk (T, L): 16 tiles x 32 contiguous pts.
                // Warp covers 2 tiles/iter: lane -> tile 2i + (lane>>4), pair L*16 + (lane&15).
                float p1d = FLT_MAX, p2d = FLT_MAX;
                int   p1i = 0x7fffffff, p2i = 0x7fffffff;
                #pragma unroll 2
                for (int i = 0; i < 8; i++) {
                    const int r = 2 * i + (lane >> 4);
                    const int fidx = T * (PN / 4) + r * 512 + L * 16 + (lane & 15);
                    const float4 va = gA[fidx];
                    const float4 vb = gB[fidx];
                    const int n0 = 2 * fidx;
                    {
                        const float d = dist_d(va.x, va.z, vb.x, vb.z, qx, qy, qz, a2);
                        const bool lt1 = d < p1d;
                        const bool lt2 = d < p2d;
                        p2d = lt1 ? p1d : (lt2 ? d : p2d);
                        p2i = lt1 ? p1i : (lt2 ? n0 : p2i);
                        p1d = lt1 ? d   : p1d;
                        p1i = lt1 ? n0  : p1i;
                    }
                    {
                        const int n1 = n0 + 1;
                        const float d = dist_d(va.y, va.w, vb.y, vb.w, qx, qy, qz, a2);
                        const bool lt1 = d < p1d;
                        const bool lt2 = d < p2d;
                        p2d = lt1 ? p1d : (lt2 ? d : p2d);
                        p2i = lt1 ? p1i : (lt2 ? n1 : p2i);
                        p1d = lt1 ? d   : p1d;
                        p1i = lt1 ? n1  : p1i;
                    }
                }
                // Lex merge of per-lane top-2 lists
                #pragma unroll
                for (int off = 16; off > 0; off >>= 1) {
                    const float o1d = __shfl_xor_sync(0xFFFFFFFFu, p1d, off);
                    const float o2d = __shfl_xor_sync(0xFFFFFFFFu, p2d, off);
                    const int   o1i = __shfl_xor_sync(0xFFFFFFFFu, p1i, off);
                    const int   o2i = __shfl_xor_sync(0xFFFFFFFFu, p2i, off);
                    const bool aF = lex_lt(p1d, p1i, o1d, o1i);
                    const float c1 = aF ? o1d : p1d;  const int c1i = aF ? o1i : p1i;
                    const float c2 = aF ? p2d : o2d;  const int c2i = aF ? p2i : o2i;
                    const float n1 = aF ? p1d : o1d;  const int n1i = aF ? p1i : o1i;
                    const bool t1 = lex_lt(c1, c1i, c2, c2i);
                    p1d = n1; p1i = n1i;
                    p2d = t1 ? c1 : c2; p2i = t1 ? c1i : c2i;
                }
                const float w1d = __shfl_sync(0xFFFFFFFFu, p1d, 0);
                const int   w1i = __shfl_sync(0xFFFFFFFFu, p1i, 0);
                const float w2d = __shfl_sync(0xFFFFFFFFu, p2d, 0);
                const int   w2i = __shfl_sync(0xFFFFFFFFu, p2i, 0);

                // Merge disjoint-set top-2 lists
                const bool aF = lex_lt(g1d, g1i, w1d, w1i);
                const float c1 = aF ? w1d : g1d;  const int c1i = aF ? w1i : g1i;
                const float c2 = aF ? g2d : w2d;  const int c2i = aF ? g2i : w2i;
                const float n1 = aF ? g1d : w1d;  const int n1i = aF ? g1i : w1i;
                const bool t1 = lex_lt(c1, c1i, c2, c2i);
                g1d = n1; g1i = n1i;
                g2d = t1 ? c1 : c2; g2i = t1 ? c1i : c2i;
            }
        }

        const int sel = g2i;   // stable 2nd-nearest index

        // Gather feature row (256 floats), warp-coalesced
        const float4* __restrict__ srow = reinterpret_cast<const float4*>(feats + (size_t)sel * PC);
        float4* __restrict__ drow = reinterpret_cast<float4*>(out_side + (size_t)qo * PC);
        #pragma unroll
        for (int k = lane; k < PC / 4; k += 32) {
            drow[k] = srow[k];
        }
    }
}

extern "C" void kernel_launch(void* const* d_in, const int* in_sizes, int n_in,
                              void* d_out, int out_size)
{
    const float* src        = (const float*)d_in[0];
    const float* tgt        = (const float*)d_in[1];
    const float* src_coords = (const float*)d_in[2];
    const float* tgt_coords = (const float*)d_in[3];
    const float* src_sc     = (const float*)d_in[4];
    const float* tgt_sc     = (const float*)d_in[5];
    float* out = (float*)d_out;

    dim3 pgrid(PN / 2 / 256, 2);
    pack_kernel<<<pgrid, 256>>>(src_coords, tgt_coords);

    dim3 grid(PM / QPB, 2);
    closest_pool_main<<<grid, BLOCK>>>(src, tgt, src_sc, tgt_sc, out);
}

// round 14
// speedup vs baseline: 2.0051x; 1.0317x over previous
#include <cuda_runtime.h>
#include <float.h>
#include <stdint.h>

// Problem constants
#define PN 32768   // points per side
#define PM 8192    // shortcut (query) points per side
#define PC 256     // feature channels

#define TEAMS 4          // split-N teams per block (each scans PN/4)
#define TSP 512          // tile points per team per iteration
#define TILES 16         // tiles per team (TILES*TSP = PN/4)
#define WARPS 8
#define BLOCK (WARPS * 32)
#define QPW 8            // queries per warp (4 f32x2 pairs)
#define QPB 16           // queries per block (2 octets x 8)

// Single packed coord array: (x, y, z, b2) per point. b2 computed once;
// mainloop and rescan read identical bits.
__device__ float4 g_P[2][PN];

__forceinline__ __device__ float sqnorm3(float x, float y, float z) {
    return (x * x + y * y) + z * z;
}

// Scalar distance — bit-identical to the packed f32x2 path (IEEE per-component),
// same sequence as the R1 kernel that measured rel_err == 0.0.
__forceinline__ __device__ float dist_d(float x, float y, float z, float b2,
                                        float qx, float qy, float qz, float a2) {
    const float dot = fmaf(x, qx, fmaf(y, qy, z * qz));
    const float t   = a2 + b2;
    return fmaf(-2.0f, dot, t);
}

// Packed f32x2 ops (sm_103a)
#define FMA2(r, a, b, c) asm("fma.rn.f32x2 %0, %1, %2, %3;" : "=l"(r) : "l"(a), "l"(b), "l"(c))
#define MUL2(r, a, b)    asm("mul.rn.f32x2 %0, %1, %2;"     : "=l"(r) : "l"(a), "l"(b))
#define ADD2(r, a, b)    asm("add.rn.f32x2 %0, %1, %2;"     : "=l"(r) : "l"(a), "l"(b))
#define PACK2(r, lo, hi) asm("mov.b64 %0, {%1, %2};" : "=l"(r) : "f"(lo), "f"(hi))
#define UNPACK2(lo, hi, r) asm("mov.b64 {%0, %1}, %2;" : "=f"(lo), "=f"(hi) : "l"(r))

__forceinline__ __device__ bool lex_lt(float da, int ia, float db, int ib) {
    return (da < db) || (da == db && ia < ib);
}

__global__ void pack_kernel(const float* __restrict__ src_coords,
                            const float* __restrict__ tgt_coords) {
    const int n = blockIdx.x * blockDim.x + threadIdx.x;
    const int side = blockIdx.y;
    const float* __restrict__ c = side ? tgt_coords : src_coords;
    const float x = c[n * 3 + 0];
    const float y = c[n * 3 + 1];
    const float z = c[n * 3 + 2];
    g_P[side][n] = make_float4(x, y, z, sqnorm3(x, y, z));
}

__global__ __launch_bounds__(BLOCK, 4) void closest_pool_main(
    const float* __restrict__ src_feats,
    const float* __restrict__ tgt_feats,
    const float* __restrict__ src_sc,
    const float* __restrict__ tgt_sc,
    float* __restrict__ out)
{
    // Per-team tile buffers; rotation swizzle within each lane's 16-slot chunk:
    // logical (L, v) -> physical L*16 + ((v + L) & 15) -> 4-phase (optimal) LDS.128.
    __shared__ __align__(16) float4 sh[TEAMS][TSP];     // 32 KB
    __shared__ float minv[QPB][TEAMS * 32];             // 8 KB: [query][chunk]

    const int side = blockIdx.y;
    const float* __restrict__ feats = side ? tgt_feats : src_feats;
    const float* __restrict__ qc    = side ? tgt_sc    : src_sc;
    float* __restrict__ out_side = out + (size_t)side * PM * PC;

    const float4* __restrict__ gP = g_P[side];

    const int warp  = threadIdx.x >> 5;
    const int lane  = threadIdx.x & 31;
    const int team  = warp >> 1;            // 0..3: scans points [team*8192, +8192)
    const int octet = warp & 1;             // which 8 queries of the block

    // Query packs: 4 f32x2 pairs, pair j = queries (octet*8 + 2j, +1)
    unsigned long long qxp[4], qyp[4], qzp[4], qap[4], NEG2;
    #pragma unroll
    for (int j = 0; j < 4; j++) {
        const int q0 = blockIdx.x * QPB + octet * 8 + 2 * j;
        const float qx0 = qc[q0 * 3 + 0], qy0 = qc[q0 * 3 + 1], qz0 = qc[q0 * 3 + 2];
        const float qx1 = qc[q0 * 3 + 3], qy1 = qc[q0 * 3 + 4], qz1 = qc[q0 * 3 + 5];
        const float a20 = sqnorm3(qx0, qy0, qz0);
        const float a21 = sqnorm3(qx1, qy1, qz1);
        PACK2(qxp[j], qx0, qx1);
        PACK2(qyp[j], qy0, qy1);
        PACK2(qzp[j], qz0, qz1);
        PACK2(qap[j], a20, a21);
    }
    { const float m2 = -2.0f; PACK2(NEG2, m2, m2); }

    float dmin[QPW];
    #pragma unroll
    for (int j = 0; j < QPW; j++) dmin[j] = FLT_MAX;

    #pragma unroll 1
    for (int r = 0; r < TILES; r++) {
        __syncthreads();
        // Fill all 4 team buffers (2048 pts, 32 KB), coalesced LDG + swizzled STS.
        #pragma unroll
        for (int t = threadIdx.x; t < TEAMS * TSP; t += BLOCK) {
            const int b = t >> 9;
            const int p = t & 511;
            const int L = p >> 4, v = p & 15;
            const int phys = (L << 4) | ((v + L) & 15);
            sh[b][phys] = gP[b * (PN / 4) + r * TSP + p];
        }
        __syncthreads();

        // 16 v-steps; lane owns points [lane*16, +16) of its team's tile.
        #pragma unroll 8
        for (int v = 0; v < 16; v++) {
            const int idx = (lane << 4) | ((v + lane) & 15);
            const float4 pt = sh[team][idx];        // (x, y, z, b2)
            unsigned long long xx, yy, zz, bb;
            PACK2(xx, pt.x, pt.x);
            PACK2(yy, pt.y, pt.y);
            PACK2(zz, pt.z, pt.z);
            PACK2(bb, pt.w, pt.w);
            #pragma unroll
            for (int j = 0; j < 4; j++) {
                unsigned long long acc, dot2, d2v;
                MUL2(acc, zz, qzp[j]);
                FMA2(dot2, yy, qyp[j], acc);
                FMA2(dot2, xx, qxp[j], dot2);
                ADD2(acc, qap[j], bb);
                FMA2(d2v, NEG2, dot2, acc);
                float dlo, dhi;
                UNPACK2(dlo, dhi, d2v);
                dmin[2 * j]     = fminf(dmin[2 * j],     dlo);
                dmin[2 * j + 1] = fminf(dmin[2 * j + 1], dhi);
            }
        }
    }

    // Publish chunk minima: chunk c = team*32 + lane owns 256 pts
    // { team*8192 + r*512 + lane*16 + [0,16) : r in [0,16) }
    __syncthreads();
    #pragma unroll
    for (int j = 0; j < QPW; j++)
        minv[octet * 8 + j][team * 32 + lane] = dmin[j];
    __syncthreads();

    // ---- Epilogue: each warp finishes 2 queries ----
    #pragma unroll 1
    for (int e = 0; e < 2; e++) {
        const int q  = warp * 2 + e;
        const int qo = blockIdx.x * QPB + q;
        const float qx = qc[qo * 3 + 0];
        const float qy = qc[qo * 3 + 1];
        const float qz = qc[qo * 3 + 2];
        const float a2 = sqnorm3(qx, qy, qz);

        float m[TEAMS];
        #pragma unroll
        for (int T = 0; T < TEAMS; T++) m[T] = minv[q][T * 32 + lane];

        // Lane-local top-2 (with multiplicity) of its 4 chunk minima
        float bd = m[0], sd = FLT_MAX;
        #pragma unroll
        for (int T = 1; T < TEAMS; T++) {
            const float mx = fmaxf(bd, m[T]);
            bd = fminf(bd, m[T]);
            sd = fminf(sd, mx);
        }
        // Warp top-2 multiset merge over all 128 chunk minima
        #pragma unroll
        for (int off = 16; off > 0; off >>= 1) {
            const float ob = __shfl_xor_sync(0xFFFFFFFFu, bd, off);
            const float os = __shfl_xor_sync(0xFFFFFFFFu, sd, off);
            const float mx = fmaxf(bd, ob);
            bd = fminf(bd, ob);
            sd = fminf(fminf(sd, os), mx);
        }
        // Candidate chunks: min in {bd, sd}
        unsigned mask[TEAMS];
        #pragma unroll
        for (int T = 0; T < TEAMS; T++)
            mask[T] = __ballot_sync(0xFFFFFFFFu, m[T] == bd || m[T] == sd);

        float g1d = FLT_MAX, g2d = FLT_MAX;
        int   g1i = 0x7fffffff, g2i = 0x7fffffff;

        #pragma unroll 1
        for (int T = 0; T < TEAMS; T++) {
            unsigned mk = mask[T];
            while (mk) {
                const int L = __ffs(mk) - 1;
                mk &= mk - 1;

                // Coalesced rescan of chunk (T, L): 16 tiles x 16 contiguous pts.
                // Warp covers 2 tiles/iter: lane -> tile 2i+(lane>>4), pt L*16+(lane&15).
                float p1d = FLT_MAX, p2d = FLT_MAX;
                int   p1i = 0x7fffffff, p2i = 0x7fffffff;
                #pragma unroll 2
                for (int i = 0; i < 8; i++) {
                    const int rr = 2 * i + (lane >> 4);
                    const int n  = T * (PN / 4) + rr * TSP + L * 16 + (lane & 15);
                    const float4 p = gP[n];
                    const float d = dist_d(p.x, p.y, p.z, p.w, qx, qy, qz, a2);
                    const bool lt1 = d < p1d;
                    const bool lt2 = d < p2d;
                    p2d = lt1 ? p1d : (lt2 ? d : p2d);
                    p2i = lt1 ? p1i : (lt2 ? n : p2i);
                    p1d = lt1 ? d   : p1d;
                    p1i = lt1 ? n   : p1i;
                }
                // Lex merge of per-lane top-2 lists
                #pragma unroll
                for (int off = 16; off > 0; off >>= 1) {
                    const float o1d = __shfl_xor_sync(0xFFFFFFFFu, p1d, off);
                    const float o2d = __shfl_xor_sync(0xFFFFFFFFu, p2d, off);
                    const int   o1i = __shfl_xor_sync(0xFFFFFFFFu, p1i, off);
                    const int   o2i = __shfl_xor_sync(0xFFFFFFFFu, p2i, off);
                    const bool aF = lex_lt(p1d, p1i, o1d, o1i);
                    const float c1 = aF ? o1d : p1d;  const int c1i = aF ? o1i : p1i;
                    const float c2 = aF ? p2d : o2d;  const int c2i = aF ? p2i : o2i;
                    const float n1 = aF ? p1d : o1d;  const int n1i = aF ? p1i : o1i;
                    const bool t1 = lex_lt(c1, c1i, c2, c2i);
                    p1d = n1; p1i = n1i;
                    p2d = t1 ? c1 : c2; p2i = t1 ? c1i : c2i;
                }
                const float w1d = __shfl_sync(0xFFFFFFFFu, p1d, 0);
                const int   w1i = __shfl_sync(0xFFFFFFFFu, p1i, 0);
                const float w2d = __shfl_sync(0xFFFFFFFFu, p2d, 0);
                const int   w2i = __shfl_sync(0xFFFFFFFFu, p2i, 0);

                // Merge disjoint-set top-2 lists
                const bool aF = lex_lt(g1d, g1i, w1d, w1i);
                const float c1 = aF ? w1d : g1d;  const int c1i = aF ? w1i : g1i;
                const float c2 = aF ? g2d : w2d;  const int c2i = aF ? g2i : w2i;
                const float n1 = aF ? g1d : w1d;  const int n1i = aF ? g1i : w1i;
                const bool t1 = lex_lt(c1, c1i, c2, c2i);
                g1d = n1; g1i = n1i;
                g2d = t1 ? c1 : c2; g2i = t1 ? c1i : c2i;
            }
        }

        const int sel = g2i;   // stable 2nd-nearest index

        // Gather feature row (256 floats), warp-coalesced
        const float4* __restrict__ srow = reinterpret_cast<const float4*>(feats + (size_t)sel * PC);
        float4* __restrict__ drow = reinterpret_cast<float4*>(out_side + (size_t)qo * PC);
        #pragma unroll
        for (int k = lane; k < PC / 4; k += 32) {
            drow[k] = srow[k];
        }
    }
}

extern "C" void kernel_launch(void* const* d_in, const int* in_sizes, int n_in,
                              void* d_out, int out_size)
{
    const float* src        = (const float*)d_in[0];
    const float* tgt        = (const float*)d_in[1];
    const float* src_coords = (const float*)d_in[2];
    const float* tgt_coords = (const float*)d_in[3];
    const float* src_sc     = (const float*)d_in[4];
    const float* tgt_sc     = (const float*)d_in[5];
    float* out = (float*)d_out;

    dim3 pgrid(PN / 256, 2);
    pack_kernel<<<pgrid, 256>>>(src_coords, tgt_coords);

    dim3 grid(PM / QPB, 2);
    closest_pool_main<<<grid, BLOCK>>>(src, tgt, src_sc, tgt_sc, out);
}

// round 17
// speedup vs baseline: 2.1332x; 1.0639x over previous
#include <cuda_runtime.h>
#include <float.h>
#include <stdint.h>

// Problem constants
#define PN 32768   // points per side
#define PM 8192    // shortcut (query) points per side
#define PC 256     // feature channels

#define TEAMS 4          // split-N teams per block (each scans PN/4)
#define TSP 256          // tile points per team per iteration
#define TILES 32         // tiles per team (TILES*TSP = PN/4)
#define WARPS 8
#define BLOCK (WARPS * 32)
#define QPW 8            // queries per warp (4 f32x2 pairs)
#define QPB 16           // queries per block (2 octets x 8)

// Single packed coord array: (x, y, z, b2) per point. b2 computed once;
// mainloop and rescan read identical bits.
__device__ float4 g_P[2][PN];

__forceinline__ __device__ float sqnorm3(float x, float y, float z) {
    return (x * x + y * y) + z * z;
}

// Scalar distance — bit-identical to the packed f32x2 path (IEEE per-component),
// same sequence as the R1 kernel that measured rel_err == 0.0.
__forceinline__ __device__ float dist_d(float x, float y, float z, float b2,
                                        float qx, float qy, float qz, float a2) {
    const float dot = fmaf(x, qx, fmaf(y, qy, z * qz));
    const float t   = a2 + b2;
    return fmaf(-2.0f, dot, t);
}

// Packed f32x2 ops (sm_103a) — NOTE: packed family is add/mul/fma only (no min).
#define FMA2(r, a, b, c) asm("fma.rn.f32x2 %0, %1, %2, %3;" : "=l"(r) : "l"(a), "l"(b), "l"(c))
#define MUL2(r, a, b)    asm("mul.rn.f32x2 %0, %1, %2;"     : "=l"(r) : "l"(a), "l"(b))
#define ADD2(r, a, b)    asm("add.rn.f32x2 %0, %1, %2;"     : "=l"(r) : "l"(a), "l"(b))
#define PACK2(r, lo, hi) asm("mov.b64 %0, {%1, %2};" : "=l"(r) : "f"(lo), "f"(hi))
#define UNPACK2(lo, hi, r) asm("mov.b64 {%0, %1}, %2;" : "=f"(lo), "=f"(hi) : "l"(r))

// cp.async 16B + pipeline control
#define CP_ASYNC16(smem_u32, gptr) \
    asm volatile("cp.async.cg.shared.global [%0], [%1], 16;" :: "r"(smem_u32), "l"(gptr))
#define CP_COMMIT() asm volatile("cp.async.commit_group;" ::: "memory")
#define CP_WAIT(N)  asm volatile("cp.async.wait_group %0;" :: "n"(N) : "memory")

__forceinline__ __device__ uint32_t smem_u32(const void* p) {
    uint32_t a;
    asm("{ .reg .u64 t; cvta.to.shared.u64 t, %1; cvt.u32.u64 %0, t; }" : "=r"(a) : "l"(p));
    return a;
}

__forceinline__ __device__ bool lex_lt(float da, int ia, float db, int ib) {
    return (da < db) || (da == db && ia < ib);
}

__global__ void pack_kernel(const float* __restrict__ src_coords,
                            const float* __restrict__ tgt_coords) {
    const int n = blockIdx.x * blockDim.x + threadIdx.x;
    const int side = blockIdx.y;
    const float* __restrict__ c = side ? tgt_coords : src_coords;
    const float x = c[n * 3 + 0];
    const float y = c[n * 3 + 1];
    const float z = c[n * 3 + 2];
    g_P[side][n] = make_float4(x, y, z, sqnorm3(x, y, z));
}

__global__ __launch_bounds__(BLOCK, 4) void closest_pool_main(
    const float* __restrict__ src_feats,
    const float* __restrict__ tgt_feats,
    const float* __restrict__ src_sc,
    const float* __restrict__ tgt_sc,
    float* __restrict__ out)
{
    // Double-buffered per-team tiles; rotation swizzle within each lane's 8-slot
    // chunk: logical (L, v) -> physical L*8 + ((v + L) & 7) -> conflict-free LDS.128.
    __shared__ __align__(16) float4 sh[2][TEAMS][TSP];   // 32 KB
    __shared__ float minv[QPB][TEAMS * 32];              // 8 KB: [query][chunk]

    const int side = blockIdx.y;
    const float* __restrict__ feats = side ? tgt_feats : src_feats;
    const float* __restrict__ qc    = side ? tgt_sc    : src_sc;
    float* __restrict__ out_side = out + (size_t)side * PM * PC;

    const float4* __restrict__ gP = g_P[side];

    const int warp  = threadIdx.x >> 5;
    const int lane  = threadIdx.x & 31;
    const int team  = warp >> 1;            // 0..3: scans points [team*8192, +8192)
    const int octet = warp & 1;             // which 8 queries of the block

    // Query packs: 4 f32x2 pairs, pair j = queries (octet*8 + 2j, +1)
    unsigned long long qxp[4], qyp[4], qzp[4], qap[4], NEG2;
    #pragma unroll
    for (int j = 0; j < 4; j++) {
        const int q0 = blockIdx.x * QPB + octet * 8 + 2 * j;
        const float qx0 = qc[q0 * 3 + 0], qy0 = qc[q0 * 3 + 1], qz0 = qc[q0 * 3 + 2];
        const float qx1 = qc[q0 * 3 + 3], qy1 = qc[q0 * 3 + 4], qz1 = qc[q0 * 3 + 5];
        const float a20 = sqnorm3(qx0, qy0, qz0);
        const float a21 = sqnorm3(qx1, qy1, qz1);
        PACK2(qxp[j], qx0, qx1);
        PACK2(qyp[j], qy0, qy1);
        PACK2(qzp[j], qz0, qz1);
        PACK2(qap[j], a20, a21);
    }
    { const float m2 = -2.0f; PACK2(NEG2, m2, m2); }

    float dmin[QPW];
    #pragma unroll
    for (int j = 0; j < QPW; j++) dmin[j] = FLT_MAX;

    const uint32_t shbase = smem_u32(&sh[0][0][0]);

    // Async fill of tile r into buffer bf: 1024 float4, 4 cp.async per thread.
    auto fill_tile = [&](int r, int bf) {
        #pragma unroll
        for (int k = 0; k < (TEAMS * TSP) / BLOCK; k++) {
            const int t = threadIdx.x + k * BLOCK;
            const int b = t >> 8;
            const int p = t & 255;
            const int L = p >> 3, v = p & 7;
            const int phys = (L << 3) | ((v + L) & 7);
            const uint32_t dst = shbase + (uint32_t)(((bf * TEAMS + b) * TSP + phys) * 16);
            CP_ASYNC16(dst, (const void*)&gP[b * (PN / 4) + r * TSP + p]);
        }
    };

    // 2-stage pipeline: prefetch r+1 while computing r.
    fill_tile(0, 0);
    CP_COMMIT();

    #pragma unroll 1
    for (int r = 0; r < TILES; r++) {
        if (r + 1 < TILES) {
            fill_tile(r + 1, (r + 1) & 1);
            CP_COMMIT();
            CP_WAIT(1);           // tile r's fill complete
        } else {
            CP_WAIT(0);
        }
        __syncthreads();

        // 8 v-steps; lane owns points [lane*8, +8) of its team's tile buffer.
        const float4* __restrict__ buf = sh[r & 1][team];
        #pragma unroll 8
        for (int v = 0; v < 8; v++) {
            const int idx = (lane << 3) | ((v + lane) & 7);
            const float4 pt = buf[idx];             // (x, y, z, b2)
            unsigned long long xx, yy, zz, bb;
            PACK2(xx, pt.x, pt.x);
            PACK2(yy, pt.y, pt.y);
            PACK2(zz, pt.z, pt.z);
            PACK2(bb, pt.w, pt.w);
            #pragma unroll
            for (int j = 0; j < 4; j++) {
                unsigned long long acc, dot2, d2v;
                MUL2(acc, zz, qzp[j]);
                FMA2(dot2, yy, qyp[j], acc);
                FMA2(dot2, xx, qxp[j], dot2);
                ADD2(acc, qap[j], bb);
                FMA2(d2v, NEG2, dot2, acc);
                float dlo, dhi;
                UNPACK2(dlo, dhi, d2v);
                dmin[2 * j]     = fminf(dmin[2 * j],     dlo);
                dmin[2 * j + 1] = fminf(dmin[2 * j + 1], dhi);
            }
        }
        __syncthreads();          // all done with buffer r&1 before it's refilled
    }

    // Publish chunk minima: chunk c = team*32 + lane owns 256 pts
    // { team*8192 + r*256 + lane*8 + [0,8) : r in [0,32) }
    #pragma unroll
    for (int j = 0; j < QPW; j++)
        minv[octet * 8 + j][team * 32 + lane] = dmin[j];
    __syncthreads();

    // ---- Epilogue: each warp finishes 2 queries ----
    #pragma unroll 1
    for (int e = 0; e < 2; e++) {
        const int q  = warp * 2 + e;
        const int qo = blockIdx.x * QPB + q;
        const float qx = qc[qo * 3 + 0];
        const float qy = qc[qo * 3 + 1];
        const float qz = qc[qo * 3 + 2];
        const float a2 = sqnorm3(qx, qy, qz);

        float m[TEAMS];
        #pragma unroll
        for (int T = 0; T < TEAMS; T++) m[T] = minv[q][T * 32 + lane];

        // Lane-local top-2 (with multiplicity) of its 4 chunk minima
        float bd = m[0], sd = FLT_MAX;
        #pragma unroll
        for (int T = 1; T < TEAMS; T++) {
            const float mx = fmaxf(bd, m[T]);
            bd = fminf(bd, m[T]);
            sd = fminf(sd, mx);
        }
        // Warp top-2 multiset merge over all 128 chunk minima
        #pragma unroll
        for (int off = 16; off > 0; off >>= 1) {
            const float ob = __shfl_xor_sync(0xFFFFFFFFu, bd, off);
            const float os = __shfl_xor_sync(0xFFFFFFFFu, sd, off);
            const float mx = fmaxf(bd, ob);
            bd = fminf(bd, ob);
            sd = fminf(fminf(sd, os), mx);
        }
        // Candidate chunks: min in {bd, sd}
        unsigned mask[TEAMS];
        #pragma unroll
        for (int T = 0; T < TEAMS; T++)
            mask[T] = __ballot_sync(0xFFFFFFFFu, m[T] == bd || m[T] == sd);

        float g1d = FLT_MAX, g2d = FLT_MAX;
        int   g1i = 0x7fffffff, g2i = 0x7fffffff;

        #pragma unroll 1
        for (int T = 0; T < TEAMS; T++) {
            unsigned mk = mask[T];
            while (mk) {
                const int L = __ffs(mk) - 1;
                mk &= mk - 1;

                // Coalesced rescan of chunk (T, L): 32 tiles x 8 contiguous pts.
                // Warp covers 4 tiles/iter: lane -> tile 4i+(lane>>3), pt L*8+(lane&7).
                float p1d = FLT_MAX, p2d = FLT_MAX;
                int   p1i = 0x7fffffff, p2i = 0x7fffffff;
                #pragma unroll 2
                for (int i = 0; i < 8; i++) {
                    const int rr = 4 * i + (lane >> 3);
                    const int n  = T * (PN / 4) + rr * TSP + L * 8 + (lane & 7);
                    const float4 p = gP[n];
                    const float d = dist_d(p.x, p.y, p.z, p.w, qx, qy, qz, a2);
                    const bool lt1 = d < p1d;
                    const bool lt2 = d < p2d;
                    p2d = lt1 ? p1d : (lt2 ? d : p2d);
                    p2i = lt1 ? p1i : (lt2 ? n : p2i);
                    p1d = lt1 ? d   : p1d;
                    p1i = lt1 ? n   : p1i;
                }
                // Lex merge of per-lane top-2 lists
                #pragma unroll
                for (int off = 16; off > 0; off >>= 1) {
                    const float o1d = __shfl_xor_sync(0xFFFFFFFFu, p1d, off);
                    const float o2d = __shfl_xor_sync(0xFFFFFFFFu, p2d, off);
                    const int   o1i = __shfl_xor_sync(0xFFFFFFFFu, p1i, off);
                    const int   o2i = __shfl_xor_sync(0xFFFFFFFFu, p2i, off);
                    const bool aF = lex_lt(p1d, p1i, o1d, o1i);
                    const float c1 = aF ? o1d : p1d;  const int c1i = aF ? o1i : p1i;
                    const float c2 = aF ? p2d : o2d;  const int c2i = aF ? p2i : o2i;
                    const float n1 = aF ? p1d : o1d;  const int n1i = aF ? p1i : o1i;
                    const bool t1 = lex_lt(c1, c1i, c2, c2i);
                    p1d = n1; p1i = n1i;
                    p2d = t1 ? c1 : c2; p2i = t1 ? c1i : c2i;
                }
                const float w1d = __shfl_sync(0xFFFFFFFFu, p1d, 0);
                const int   w1i = __shfl_sync(0xFFFFFFFFu, p1i, 0);
                const float w2d = __shfl_sync(0xFFFFFFFFu, p2d, 0);
                const int   w2i = __shfl_sync(0xFFFFFFFFu, p2i, 0);

                // Merge disjoint-set top-2 lists
                const bool aF = lex_lt(g1d, g1i, w1d, w1i);
                const float c1 = aF ? w1d : g1d;  const int c1i = aF ? w1i : g1i;
                const float c2 = aF ? g2d : w2d;  const int c2i = aF ? g2i : w2i;
                const float n1 = aF ? g1d : w1d;  const int n1i = aF ? g1i : w1i;
                const bool t1 = lex_lt(c1, c1i, c2, c2i);
                g1d = n1; g1i = n1i;
                g2d = t1 ? c1 : c2; g2i = t1 ? c1i : c2i;
            }
        }

        const int sel = g2i;   // stable 2nd-nearest index

        // Gather feature row (256 floats), warp-coalesced
        const float4* __restrict__ srow = reinterpret_cast<const float4*>(feats + (size_t)sel * PC);
        float4* __restrict__ drow = reinterpret_cast<float4*>(out_side + (size_t)qo * PC);
        #pragma unroll
        for (int k = lane; k < PC / 4; k += 32) {
            drow[k] = srow[k];
        }
    }
}

extern "C" void kernel_launch(void* const* d_in, const int* in_sizes, int n_in,
                              void* d_out, int out_size)
{
    const float* src        = (const float*)d_in[0];
    const float* tgt        = (const float*)d_in[1];
    const float* src_coords = (const float*)d_in[2];
    const float* tgt_coords = (const float*)d_in[3];
    const float* src_sc     = (const float*)d_in[4];
    const float* tgt_sc     = (const float*)d_in[5];
    float* out = (float*)d_out;

    dim3 pgrid(PN / 256, 2);
    pack_kernel<<<pgrid, 256>>>(src_coords, tgt_coords);

    dim3 grid(PM / QPB, 2);
    closest_pool_main<<<grid, BLOCK>>>(src, tgt, src_sc, tgt_sc, out);
}